// round 7
// baseline (speedup 1.0000x reference)
#include <cuda_runtime.h>

// ---------------- Problem constants ----------------
#define NMAX 100352          // >= 100000 nodes
#define EMAX 1700000         // >= 1.6M edges
#define FEAT 128             // F == H == 128

// ---------------- Device scratch (no allocs allowed) ----------------
__device__ int   g_is64;
__device__ int   g_oddnz;
__device__ int   g_cnt[NMAX];
__device__ float g_summ[NMAX];
__device__ int   g_rowptr[NMAX + 1];
__device__ int   g_wcur[NMAX];
__device__ int   g_colind[EMAX];
__device__ int   g_bsum[512];
__device__ int   g_boff[512];
__device__ float2 g_dlh[NMAX];            // packed (dl, dh)
__device__ float g_dll[NMAX], g_dhh[NMAX];
__device__ float g_wll[NMAX], g_whh[NMAX];
__device__ float g_bufA[NMAX * FEAT];
__device__ float g_bufB[NMAX * FEAT];
__device__ float g_bufC[NMAX * FEAT];
__device__ float g_bufD[NMAX * FEAT];
__device__ float g_bufE[NMAX * FEAT];

// ---------------- f32x2 packed helpers (Blackwell FFMA2) -----------------
__device__ __forceinline__ unsigned long long pack2(float v) {
    unsigned long long r;
    asm("mov.b64 %0, {%1, %1};" : "=l"(r) : "f"(v));
    return r;
}
__device__ __forceinline__ void fma2(unsigned long long& d,
                                     unsigned long long a,
                                     unsigned long long b) {
    asm("fma.rn.f32x2 %0, %1, %2, %0;" : "+l"(d) : "l"(a), "l"(b));
}
__device__ __forceinline__ float2 unpack2(unsigned long long v) {
    float lo, hi;
    asm("mov.b64 {%0, %1}, %2;" : "=f"(lo), "=f"(hi) : "l"(v));
    return make_float2(lo, hi);
}

// ---------------- dtype detector: int32 vs int64 edge_index -------------
__global__ void detectK(const int* __restrict__ ei, int nwords) {
    if (threadIdx.x == 0) g_oddnz = 0;
    __syncthreads();
    int lim = nwords < 4096 ? nwords : 4096;
    for (int i = 1 + 2 * (int)threadIdx.x; i < lim; i += 2 * (int)blockDim.x)
        if (ei[i] != 0) atomicOr(&g_oddnz, 1);
    __syncthreads();
    if (threadIdx.x == 0) g_is64 = (g_oddnz == 0) ? 1 : 0;
}

__device__ __forceinline__ void edge_fetch(const int* ei, int E, int e,
                                           int& s, int& r) {
    if (g_is64) {          // int64 little-endian: low words at even positions
        s = ei[2 * e];
        r = ei[2 * E + 2 * e];
    } else {               // int32: [src x E, dst x E]
        s = ei[e];
        r = ei[E + e];
    }
}

// ---------------- Preprocessing ----------------
__global__ void initK(int n) {
    int i = blockIdx.x * blockDim.x + threadIdx.x;
    if (i < n) { g_cnt[i] = 0; g_summ[i] = 0.f; }
}

__global__ void countK(const int* __restrict__ ei,
                       const float* __restrict__ cc, int E, int n) {
    int e = blockIdx.x * blockDim.x + threadIdx.x;
    if (e >= E) return;
    int s, r;
    edge_fetch(ei, E, e, s, r);
    if (s != r && (unsigned)s < (unsigned)n && (unsigned)r < (unsigned)n) {
        atomicAdd(&g_cnt[r], 1);
        atomicAdd(&g_summ[r], cc[s]);
    }
}

// ---------------- 3-phase grid scan over g_cnt -> rowptr, wcur ----------
__global__ void bsumK(int n) {
    __shared__ int sh[256];
    int t = threadIdx.x;
    int i = blockIdx.x * 256 + t;
    int v = (i < n) ? g_cnt[i] : 0;
    sh[t] = v;
    __syncthreads();
    for (int s = 128; s > 0; s >>= 1) {
        if (t < s) sh[t] += sh[t + s];
        __syncthreads();
    }
    if (t == 0) g_bsum[blockIdx.x] = sh[0];
}

__global__ void bscanK(int nb, int n) {   // 1 block, 512 threads
    __shared__ int sh[512];
    int t = threadIdx.x;
    int v = (t < nb) ? g_bsum[t] : 0;
    sh[t] = v;
    __syncthreads();
    for (int off = 1; off < 512; off <<= 1) {
        int u = (t >= off) ? sh[t - off] : 0;
        __syncthreads();
        sh[t] += u;
        __syncthreads();
    }
    g_boff[t] = sh[t] - v;                 // exclusive prefix
    if (t == 0) g_rowptr[n] = sh[511];     // grand total
}

__global__ void bfinalK(int n) {
    __shared__ int sh[256];
    int t = threadIdx.x;
    int i = blockIdx.x * 256 + t;
    int v = (i < n) ? g_cnt[i] : 0;
    sh[t] = v;
    __syncthreads();
    for (int off = 1; off < 256; off <<= 1) {
        int u = (t >= off) ? sh[t - off] : 0;
        __syncthreads();
        sh[t] += u;
        __syncthreads();
    }
    int excl = sh[t] - v + g_boff[blockIdx.x];
    if (i < n) { g_rowptr[i] = excl; g_wcur[i] = excl; }
}

__global__ void dinvK(const float* __restrict__ cc, int n) {
    int i = blockIdx.x * blockDim.x + threadIdx.x;
    if (i >= n) return;
    float m   = cc[i];
    float cnt = (float)g_cnt[i];
    float sm  = g_summ[i];
    float dl  = rsqrtf(m * cnt + 1.f);
    float dh  = rsqrtf((1.f - m) * cnt + 1.f);
    float dll = rsqrtf(sm + 1.f);
    float dhh = rsqrtf(cnt - sm + 1.f);
    g_dlh[i] = make_float2(dl, dh);
    g_dll[i] = dll; g_dhh[i] = dhh;
    g_wll[i] = m * dll;
    g_whh[i] = (1.f - m) * dhh;
}

__global__ void scatterK(const int* __restrict__ ei, int E, int n) {
    int e = blockIdx.x * blockDim.x + threadIdx.x;
    if (e >= E) return;
    int s, r;
    edge_fetch(ei, E, e, s, r);
    if (s != r && (unsigned)s < (unsigned)n && (unsigned)r < (unsigned)n) {
        int pos = atomicAdd(&g_wcur[r], 1);
        g_colind[pos] = s;
    }
}

// ---------------- SpMM: warp per destination row ----------------
__global__ void __launch_bounds__(256) spmm1K(const float* __restrict__ x,
                                              const float* __restrict__ cc, int n) {
    int w = (blockIdx.x * blockDim.x + threadIdx.x) >> 5;
    int lane = threadIdx.x & 31;
    if (w >= n) return;
    const float4* x4 = (const float4*)x;
    float4 al = make_float4(0.f, 0.f, 0.f, 0.f);
    float4 ah = make_float4(0.f, 0.f, 0.f, 0.f);
    int s = g_rowptr[w], e = g_rowptr[w + 1];
    for (int i = s; i < e; i++) {
        int c = g_colind[i];
        float2 wlh = g_dlh[c];
        float4 xv = __ldg(&x4[c * 32 + lane]);
        al.x = fmaf(wlh.x, xv.x, al.x); al.y = fmaf(wlh.x, xv.y, al.y);
        al.z = fmaf(wlh.x, xv.z, al.z); al.w = fmaf(wlh.x, xv.w, al.w);
        ah.x = fmaf(wlh.y, xv.x, ah.x); ah.y = fmaf(wlh.y, xv.y, ah.y);
        ah.z = fmaf(wlh.y, xv.z, ah.z); ah.w = fmaf(wlh.y, xv.w, ah.w);
    }
    float m = cc[w];
    float2 dlh = g_dlh[w];
    float4 xr = x4[w * 32 + lane];
    float sl = dlh.x * m, dl2 = dlh.x * dlh.x;
    float sh = dlh.y * (1.f - m), dh2 = dlh.y * dlh.y;
    float4 ol, oh;
    ol.x = fmaf(sl, al.x, dl2 * xr.x); ol.y = fmaf(sl, al.y, dl2 * xr.y);
    ol.z = fmaf(sl, al.z, dl2 * xr.z); ol.w = fmaf(sl, al.w, dl2 * xr.w);
    oh.x = fmaf(sh, ah.x, dh2 * xr.x); oh.y = fmaf(sh, ah.y, dh2 * xr.y);
    oh.z = fmaf(sh, ah.z, dh2 * xr.z); oh.w = fmaf(sh, ah.w, dh2 * xr.w);
    ((float4*)g_bufA)[w * 32 + lane] = ol;
    ((float4*)g_bufB)[w * 32 + lane] = oh;
}

// Layer 2 (source-masked). SEL=0: bufC->bufA with (wll,dll); SEL=1: bufD->bufB with (whh,dhh)
template<int SEL>
__global__ void __launch_bounds__(256) spmm2K(int n) {
    const float* in = (SEL == 0) ? g_bufC : g_bufD;
    float* out      = (SEL == 0) ? g_bufA : g_bufB;
    const float* wc = (SEL == 0) ? g_wll  : g_whh;
    const float* dr = (SEL == 0) ? g_dll  : g_dhh;
    int w = (blockIdx.x * blockDim.x + threadIdx.x) >> 5;
    int lane = threadIdx.x & 31;
    if (w >= n) return;
    const float4* in4 = (const float4*)in;
    float4 acc = make_float4(0.f, 0.f, 0.f, 0.f);
    int s = g_rowptr[w], e = g_rowptr[w + 1];
    for (int i = s; i < e; i++) {
        int c = g_colind[i];
        float ww = wc[c];
        float4 xv = __ldg(&in4[c * 32 + lane]);
        acc.x = fmaf(ww, xv.x, acc.x); acc.y = fmaf(ww, xv.y, acc.y);
        acc.z = fmaf(ww, xv.z, acc.z); acc.w = fmaf(ww, xv.w, acc.w);
    }
    float d = dr[w], d2 = d * d;
    float4 xr = in4[w * 32 + lane];
    float4 o;
    o.x = fmaf(d, acc.x, d2 * xr.x); o.y = fmaf(d, acc.y, d2 * xr.y);
    o.z = fmaf(d, acc.z, d2 * xr.z); o.w = fmaf(d, acc.w, d2 * xr.w);
    ((float4*)out)[w * 32 + lane] = o;
}

// ---------------- GEMM: [n x 128] @ [128 x 128], fp32, FFMA2 inner loop -----
// 128x128 tile, BK=16, double-buffered smem, 8x8 register blocking (packed
// f32x2 along columns), 256 threads.
// ASRC: 0=g_bufA, 1=g_bufB, 2=external pointer (x). CDST: 0=g_bufC, 1=g_bufD, 2=g_bufE.
template<int ASRC, int CDST, bool RELU>
__global__ void __launch_bounds__(256, 2) gemmK(const float* __restrict__ Aext,
                                                const float* __restrict__ B,
                                                int n) {
    const float* A = (ASRC == 0) ? g_bufA : (ASRC == 1) ? g_bufB : Aext;
    float* C       = (CDST == 0) ? g_bufC : (CDST == 1) ? g_bufD : g_bufE;

    __shared__ float Ast[2][16][128];   // A^T tile: Ast[k][m], 8KB per buffer
    __shared__ float Bsm[2][16][128];   // B tile:   Bsm[k][n], 8KB per buffer

    int tid = threadIdx.x;
    int bm  = blockIdx.x * 128;
    int tr  = (tid >> 4) * 8;           // output row0 within tile
    int tc  = (tid & 15) * 8;           // output col0

    int ar0 = tid >> 2, aq0 = tid & 3;          // A loader: (row, q)
    int ar1 = ar0 + 64, aq1 = aq0;
    int bk0 = tid >> 5, bn4 = tid & 31;         // B loader

    const float4* A4 = (const float4*)A;
    const float4* B4 = (const float4*)B;

    unsigned long long acc2[8][4];
    #pragma unroll
    for (int r = 0; r < 8; r++)
        #pragma unroll
        for (int c = 0; c < 4; c++) acc2[r][c] = 0ull;

    float4 pa0, pa1, pb0, pb1;

    // prefetch chunk 0
    pa0 = (bm + ar0 < n) ? A4[(bm + ar0) * 32 + aq0] : make_float4(0, 0, 0, 0);
    pa1 = (bm + ar1 < n) ? A4[(bm + ar1) * 32 + aq1] : make_float4(0, 0, 0, 0);
    pb0 = B4[(bk0)     * 32 + bn4];
    pb1 = B4[(bk0 + 8) * 32 + bn4];

    Ast[0][aq0 * 4 + 0][ar0] = pa0.x; Ast[0][aq0 * 4 + 1][ar0] = pa0.y;
    Ast[0][aq0 * 4 + 2][ar0] = pa0.z; Ast[0][aq0 * 4 + 3][ar0] = pa0.w;
    Ast[0][aq1 * 4 + 0][ar1] = pa1.x; Ast[0][aq1 * 4 + 1][ar1] = pa1.y;
    Ast[0][aq1 * 4 + 2][ar1] = pa1.z; Ast[0][aq1 * 4 + 3][ar1] = pa1.w;
    ((float4*)&Bsm[0][bk0][0])[bn4]     = pb0;
    ((float4*)&Bsm[0][bk0 + 8][0])[bn4] = pb1;
    __syncthreads();

    #pragma unroll
    for (int kc = 0; kc < 8; kc++) {
        int cur = kc & 1;
        if (kc < 7) {   // prefetch next chunk into regs (LDG overlapped with FMA)
            int ko = (kc + 1) * 4;
            pa0 = (bm + ar0 < n) ? A4[(bm + ar0) * 32 + ko + aq0] : make_float4(0, 0, 0, 0);
            pa1 = (bm + ar1 < n) ? A4[(bm + ar1) * 32 + ko + aq1] : make_float4(0, 0, 0, 0);
            pb0 = B4[((kc + 1) * 16 + bk0)     * 32 + bn4];
            pb1 = B4[((kc + 1) * 16 + bk0 + 8) * 32 + bn4];
        }
        #pragma unroll
        for (int k = 0; k < 16; k++) {
            float4 a0 = *(const float4*)&Ast[cur][k][tr];
            float4 a1 = *(const float4*)&Ast[cur][k][tr + 4];
            // B pairs come packed straight out of shared memory
            ulonglong2 q0 = *(const ulonglong2*)&Bsm[cur][k][tc];
            ulonglong2 q1 = *(const ulonglong2*)&Bsm[cur][k][tc + 4];
            unsigned long long bb[4] = {q0.x, q0.y, q1.x, q1.y};
            float av[8] = {a0.x, a0.y, a0.z, a0.w, a1.x, a1.y, a1.z, a1.w};
            #pragma unroll
            for (int r = 0; r < 8; r++) {
                unsigned long long ar = pack2(av[r]);
                fma2(acc2[r][0], ar, bb[0]);
                fma2(acc2[r][1], ar, bb[1]);
                fma2(acc2[r][2], ar, bb[2]);
                fma2(acc2[r][3], ar, bb[3]);
            }
        }
        if (kc < 7) {
            int nxt = cur ^ 1;
            Ast[nxt][aq0 * 4 + 0][ar0] = pa0.x; Ast[nxt][aq0 * 4 + 1][ar0] = pa0.y;
            Ast[nxt][aq0 * 4 + 2][ar0] = pa0.z; Ast[nxt][aq0 * 4 + 3][ar0] = pa0.w;
            Ast[nxt][aq1 * 4 + 0][ar1] = pa1.x; Ast[nxt][aq1 * 4 + 1][ar1] = pa1.y;
            Ast[nxt][aq1 * 4 + 2][ar1] = pa1.z; Ast[nxt][aq1 * 4 + 3][ar1] = pa1.w;
            ((float4*)&Bsm[nxt][bk0][0])[bn4]     = pb0;
            ((float4*)&Bsm[nxt][bk0 + 8][0])[bn4] = pb1;
        }
        __syncthreads();
    }

    float4* C4 = (float4*)C;
    #pragma unroll
    for (int r = 0; r < 8; r++) {
        int row = bm + tr + r;
        if (row >= n) break;
        float2 p0 = unpack2(acc2[r][0]);
        float2 p1 = unpack2(acc2[r][1]);
        float2 p2 = unpack2(acc2[r][2]);
        float2 p3 = unpack2(acc2[r][3]);
        float4 o0 = make_float4(p0.x, p0.y, p1.x, p1.y);
        float4 o1 = make_float4(p2.x, p2.y, p3.x, p3.y);
        if (RELU) {
            o0.x = fmaxf(o0.x, 0.f); o0.y = fmaxf(o0.y, 0.f);
            o0.z = fmaxf(o0.z, 0.f); o0.w = fmaxf(o0.w, 0.f);
            o1.x = fmaxf(o1.x, 0.f); o1.y = fmaxf(o1.y, 0.f);
            o1.z = fmaxf(o1.z, 0.f); o1.w = fmaxf(o1.w, 0.f);
        }
        C4[row * 32 + (tc >> 2)]     = o0;
        C4[row * 32 + (tc >> 2) + 1] = o1;
    }
}

// ---------------- Fused epilogue: gate + relu + [128x10] projection ----------
__global__ void __launch_bounds__(256) epiK(const float* __restrict__ cc,
                                            const float* __restrict__ lam1,
                                            const float* __restrict__ lam2,
                                            const float* __restrict__ lw,
                                            const float* __restrict__ lb,
                                            float* __restrict__ out, int n) {
    __shared__ float sw[1280];
    int tid = threadIdx.x;
    for (int i = tid; i < 1280; i += 256) sw[i] = lw[i];
    __syncthreads();
    int w = (blockIdx.x << 3) + (tid >> 5);
    int lane = tid & 31;
    if (w >= n) return;

    float lamxl = 1.f / (1.f + expf(lam1[1] - lam1[0]));
    float laml  = 1.f - lamxl;
    float lamxh = 1.f / (1.f + expf(lam2[1] - lam2[0]));
    float lamh  = 1.f - lamxh;
    float m = cc[w];
    float lamx = lamxl * m + lamxh * (1.f - m);

    float4 fc = ((const float4*)g_bufE)[w * 32 + lane];
    float4 fl = ((const float4*)g_bufC)[w * 32 + lane];
    float4 fh = ((const float4*)g_bufD)[w * 32 + lane];
    float4 g;
    g.x = fmaxf(0.f, lamx * fc.x + laml * fl.x + lamh * fh.x);
    g.y = fmaxf(0.f, lamx * fc.y + laml * fl.y + lamh * fh.y);
    g.z = fmaxf(0.f, lamx * fc.z + laml * fl.z + lamh * fh.z);
    g.w = fmaxf(0.f, lamx * fc.w + laml * fl.w + lamh * fh.w);

    int base = lane * 40;  // (lane*4) * 10
    #pragma unroll
    for (int c = 0; c < 10; c++) {
        float p = g.x * sw[base + c] + g.y * sw[base + 10 + c] +
                  g.z * sw[base + 20 + c] + g.w * sw[base + 30 + c];
        #pragma unroll
        for (int off = 16; off > 0; off >>= 1)
            p += __shfl_xor_sync(0xffffffffu, p, off);
        if (lane == 0) out[w * 10 + c] = p + lb[c];
    }
}

// ---------------- Launch (kernel launches ONLY, no host API) ----------------
extern "C" void kernel_launch(void* const* d_in, const int* in_sizes, int n_in,
                              void* d_out, int out_size) {
    const float* x    = (const float*)d_in[0];
    const int*   ei   = (const int*)d_in[1];       // int32 (or int64 low-words; detected)
    const float* cc   = (const float*)d_in[2];
    const float* W1L  = (const float*)d_in[3];
    const float* W1H  = (const float*)d_in[4];
    const float* W2L  = (const float*)d_in[5];
    const float* W2H  = (const float*)d_in[6];
    const float* WX   = (const float*)d_in[7];
    const float* lam1 = (const float*)d_in[8];
    const float* lam2 = (const float*)d_in[9];
    const float* lw   = (const float*)d_in[10];
    const float* lb   = (const float*)d_in[11];
    float*       out  = (float*)d_out;

    int n = in_sizes[2];        // cc_mask element count == N
    int E = in_sizes[1] / 2;    // element count / 2, dtype-independent

    int nbN = (n + 255) / 256;
    int nbE = (E + 255) / 256;
    int nbW = (n + 7) / 8;      // warp-per-row kernels, 8 warps/block
    int nbG = (n + 127) / 128;  // GEMM 128-row tiles

    detectK<<<1, 256>>>(ei, in_sizes[1]);
    initK<<<nbN, 256>>>(n);
    countK<<<nbE, 256>>>(ei, cc, E, n);
    bsumK<<<nbN, 256>>>(n);
    bscanK<<<1, 512>>>(nbN, n);
    bfinalK<<<nbN, 256>>>(n);
    dinvK<<<nbN, 256>>>(cc, n);
    scatterK<<<nbE, 256>>>(ei, E, n);

    spmm1K<<<nbW, 256>>>(x, cc, n);                     // -> bufA (yl), bufB (yh)
    gemmK<0, 0, true ><<<nbG, 256>>>(nullptr, W1L, n);  // bufC = relu(bufA @ W1L)
    gemmK<1, 1, true ><<<nbG, 256>>>(nullptr, W1H, n);  // bufD = relu(bufB @ W1H)
    spmm2K<0><<<nbW, 256>>>(n);                         // bufA = Ahat_ll @ bufC
    spmm2K<1><<<nbW, 256>>>(n);                         // bufB = Ahat_hh @ bufD
    gemmK<0, 0, false><<<nbG, 256>>>(nullptr, W2L, n);  // bufC = bufA @ W2L  (xl)
    gemmK<1, 1, false><<<nbG, 256>>>(nullptr, W2H, n);  // bufD = bufB @ W2H  (xh)
    gemmK<2, 2, false><<<nbG, 256>>>(x, WX, n);         // bufE = x @ WX      (xc)
    epiK<<<nbW, 256>>>(cc, lam1, lam2, lw, lb, out, n);
}

// round 8
// speedup vs baseline: 1.3387x; 1.3387x over previous
#include <cuda_runtime.h>

// ---------------- Problem constants ----------------
#define NMAX 100352          // >= 100000 nodes
#define EMAX 1700000         // >= 1.6M edges
#define FEAT 128             // F == H == 128

// ---------------- Device scratch (no allocs allowed) ----------------
__device__ int   g_is64;
__device__ int   g_oddnz;
__device__ int   g_cnt[NMAX];
__device__ float g_summ[NMAX];
__device__ int   g_rowptr[NMAX + 1];
__device__ int   g_wcur[NMAX];
__device__ int   g_colind[EMAX];
__device__ int   g_bsum[512];
__device__ int   g_boff[512];
__device__ float2 g_dlh[NMAX];            // packed (dl, dh)
__device__ float g_dll[NMAX], g_dhh[NMAX];
__device__ float g_wll[NMAX], g_whh[NMAX];
__device__ float g_bufA[NMAX * FEAT];
__device__ float g_bufB[NMAX * FEAT];
__device__ float g_bufC[NMAX * FEAT];
__device__ float g_bufD[NMAX * FEAT];
__device__ float g_bufE[NMAX * FEAT];

// ---------------- tf32 helpers -----------------
__device__ __forceinline__ float tf32r(float x) {
    unsigned u;
    asm("cvt.rna.tf32.f32 %0, %1;" : "=r"(u) : "f"(x));
    return __uint_as_float(u);
}

__device__ __forceinline__ void mma8(float4& d,
                                     unsigned a0, unsigned a1, unsigned a2, unsigned a3,
                                     unsigned b0, unsigned b1) {
    asm("mma.sync.aligned.m16n8k8.row.col.f32.tf32.tf32.f32 "
        "{%0,%1,%2,%3}, {%4,%5,%6,%7}, {%8,%9}, {%0,%1,%2,%3};"
        : "+f"(d.x), "+f"(d.y), "+f"(d.z), "+f"(d.w)
        : "r"(a0), "r"(a1), "r"(a2), "r"(a3), "r"(b0), "r"(b1));
}

// ---------------- dtype detector: int32 vs int64 edge_index -------------
__global__ void detectK(const int* __restrict__ ei, int nwords) {
    if (threadIdx.x == 0) g_oddnz = 0;
    __syncthreads();
    int lim = nwords < 4096 ? nwords : 4096;
    for (int i = 1 + 2 * (int)threadIdx.x; i < lim; i += 2 * (int)blockDim.x)
        if (ei[i] != 0) atomicOr(&g_oddnz, 1);
    __syncthreads();
    if (threadIdx.x == 0) g_is64 = (g_oddnz == 0) ? 1 : 0;
}

__device__ __forceinline__ void edge_fetch(const int* ei, int E, int e,
                                           int& s, int& r) {
    if (g_is64) {          // int64 little-endian: low words at even positions
        s = ei[2 * e];
        r = ei[2 * E + 2 * e];
    } else {               // int32: [src x E, dst x E]
        s = ei[e];
        r = ei[E + e];
    }
}

// ---------------- Preprocessing ----------------
__global__ void initK(int n) {
    int i = blockIdx.x * blockDim.x + threadIdx.x;
    if (i < n) { g_cnt[i] = 0; g_summ[i] = 0.f; }
}

__global__ void countK(const int* __restrict__ ei,
                       const float* __restrict__ cc, int E, int n) {
    int e = blockIdx.x * blockDim.x + threadIdx.x;
    if (e >= E) return;
    int s, r;
    edge_fetch(ei, E, e, s, r);
    if (s != r && (unsigned)s < (unsigned)n && (unsigned)r < (unsigned)n) {
        atomicAdd(&g_cnt[r], 1);
        atomicAdd(&g_summ[r], cc[s]);
    }
}

// ---------------- 3-phase grid scan over g_cnt -> rowptr, wcur ----------
__global__ void bsumK(int n) {
    __shared__ int sh[256];
    int t = threadIdx.x;
    int i = blockIdx.x * 256 + t;
    int v = (i < n) ? g_cnt[i] : 0;
    sh[t] = v;
    __syncthreads();
    for (int s = 128; s > 0; s >>= 1) {
        if (t < s) sh[t] += sh[t + s];
        __syncthreads();
    }
    if (t == 0) g_bsum[blockIdx.x] = sh[0];
}

__global__ void bscanK(int nb, int n) {   // 1 block, 512 threads
    __shared__ int sh[512];
    int t = threadIdx.x;
    int v = (t < nb) ? g_bsum[t] : 0;
    sh[t] = v;
    __syncthreads();
    for (int off = 1; off < 512; off <<= 1) {
        int u = (t >= off) ? sh[t - off] : 0;
        __syncthreads();
        sh[t] += u;
        __syncthreads();
    }
    g_boff[t] = sh[t] - v;                 // exclusive prefix
    if (t == 0) g_rowptr[n] = sh[511];     // grand total
}

__global__ void bfinalK(int n) {
    __shared__ int sh[256];
    int t = threadIdx.x;
    int i = blockIdx.x * 256 + t;
    int v = (i < n) ? g_cnt[i] : 0;
    sh[t] = v;
    __syncthreads();
    for (int off = 1; off < 256; off <<= 1) {
        int u = (t >= off) ? sh[t - off] : 0;
        __syncthreads();
        sh[t] += u;
        __syncthreads();
    }
    int excl = sh[t] - v + g_boff[blockIdx.x];
    if (i < n) { g_rowptr[i] = excl; g_wcur[i] = excl; }
}

__global__ void dinvK(const float* __restrict__ cc, int n) {
    int i = blockIdx.x * blockDim.x + threadIdx.x;
    if (i >= n) return;
    float m   = cc[i];
    float cnt = (float)g_cnt[i];
    float sm  = g_summ[i];
    float dl  = rsqrtf(m * cnt + 1.f);
    float dh  = rsqrtf((1.f - m) * cnt + 1.f);
    float dll = rsqrtf(sm + 1.f);
    float dhh = rsqrtf(cnt - sm + 1.f);
    g_dlh[i] = make_float2(dl, dh);
    g_dll[i] = dll; g_dhh[i] = dhh;
    g_wll[i] = m * dll;
    g_whh[i] = (1.f - m) * dhh;
}

__global__ void scatterK(const int* __restrict__ ei, int E, int n) {
    int e = blockIdx.x * blockDim.x + threadIdx.x;
    if (e >= E) return;
    int s, r;
    edge_fetch(ei, E, e, s, r);
    if (s != r && (unsigned)s < (unsigned)n && (unsigned)r < (unsigned)n) {
        int pos = atomicAdd(&g_wcur[r], 1);
        g_colind[pos] = s;
    }
}

// ---------------- SpMM: warp per destination row ----------------
__global__ void __launch_bounds__(256) spmm1K(const float* __restrict__ x,
                                              const float* __restrict__ cc, int n) {
    int w = (blockIdx.x * blockDim.x + threadIdx.x) >> 5;
    int lane = threadIdx.x & 31;
    if (w >= n) return;
    const float4* x4 = (const float4*)x;
    float4 al = make_float4(0.f, 0.f, 0.f, 0.f);
    float4 ah = make_float4(0.f, 0.f, 0.f, 0.f);
    int s = g_rowptr[w], e = g_rowptr[w + 1];
    for (int i = s; i < e; i++) {
        int c = g_colind[i];
        float2 wlh = g_dlh[c];
        float4 xv = __ldg(&x4[c * 32 + lane]);
        al.x = fmaf(wlh.x, xv.x, al.x); al.y = fmaf(wlh.x, xv.y, al.y);
        al.z = fmaf(wlh.x, xv.z, al.z); al.w = fmaf(wlh.x, xv.w, al.w);
        ah.x = fmaf(wlh.y, xv.x, ah.x); ah.y = fmaf(wlh.y, xv.y, ah.y);
        ah.z = fmaf(wlh.y, xv.z, ah.z); ah.w = fmaf(wlh.y, xv.w, ah.w);
    }
    float m = cc[w];
    float2 dlh = g_dlh[w];
    float4 xr = x4[w * 32 + lane];
    float sl = dlh.x * m, dl2 = dlh.x * dlh.x;
    float sh = dlh.y * (1.f - m), dh2 = dlh.y * dlh.y;
    float4 ol, oh;
    ol.x = fmaf(sl, al.x, dl2 * xr.x); ol.y = fmaf(sl, al.y, dl2 * xr.y);
    ol.z = fmaf(sl, al.z, dl2 * xr.z); ol.w = fmaf(sl, al.w, dl2 * xr.w);
    oh.x = fmaf(sh, ah.x, dh2 * xr.x); oh.y = fmaf(sh, ah.y, dh2 * xr.y);
    oh.z = fmaf(sh, ah.z, dh2 * xr.z); oh.w = fmaf(sh, ah.w, dh2 * xr.w);
    ((float4*)g_bufA)[w * 32 + lane] = ol;
    ((float4*)g_bufB)[w * 32 + lane] = oh;
}

// Layer 2 (source-masked). SEL=0: bufC->bufA with (wll,dll); SEL=1: bufD->bufB with (whh,dhh)
template<int SEL>
__global__ void __launch_bounds__(256) spmm2K(int n) {
    const float* in = (SEL == 0) ? g_bufC : g_bufD;
    float* out      = (SEL == 0) ? g_bufA : g_bufB;
    const float* wc = (SEL == 0) ? g_wll  : g_whh;
    const float* dr = (SEL == 0) ? g_dll  : g_dhh;
    int w = (blockIdx.x * blockDim.x + threadIdx.x) >> 5;
    int lane = threadIdx.x & 31;
    if (w >= n) return;
    const float4* in4 = (const float4*)in;
    float4 acc = make_float4(0.f, 0.f, 0.f, 0.f);
    int s = g_rowptr[w], e = g_rowptr[w + 1];
    for (int i = s; i < e; i++) {
        int c = g_colind[i];
        float ww = wc[c];
        float4 xv = __ldg(&in4[c * 32 + lane]);
        acc.x = fmaf(ww, xv.x, acc.x); acc.y = fmaf(ww, xv.y, acc.y);
        acc.z = fmaf(ww, xv.z, acc.z); acc.w = fmaf(ww, xv.w, acc.w);
    }
    float d = dr[w], d2 = d * d;
    float4 xr = in4[w * 32 + lane];
    float4 o;
    o.x = fmaf(d, acc.x, d2 * xr.x); o.y = fmaf(d, acc.y, d2 * xr.y);
    o.z = fmaf(d, acc.z, d2 * xr.z); o.w = fmaf(d, acc.w, d2 * xr.w);
    ((float4*)out)[w * 32 + lane] = o;
}

// ---------------- GEMM: [n x 128] @ [128 x 128] via 3xTF32 tensor mma -------
// Block: 128 rows, 8 warps; warp owns 16 rows x 128 cols (16 n8-tiles).
// B processed in 32-k chunks, converted to tf32 hi/lo fragment-ordered smem.
// A fragments loaded from global (each element once/block), split in regs.
// D += Ahi*Bhi + Ahi*Blo + Alo*Bhi  (3xTF32: fp32-grade accuracy).
// ASRC: 0=g_bufA, 1=g_bufB, 2=external (x). CDST: 0=g_bufC, 1=g_bufD, 2=g_bufE.
template<int ASRC, int CDST, bool RELU>
__global__ void __launch_bounds__(256) gemmT(const float* __restrict__ Aext,
                                             const float* __restrict__ B,
                                             int n) {
    const float* A = (ASRC == 0) ? g_bufA : (ASRC == 1) ? g_bufB : Aext;
    float* C       = (CDST == 0) ? g_bufC : (CDST == 1) ? g_bufD : g_bufE;

    // fragment-ordered B: [kstep(4)][tile(16)][lane(32)][slot(2)] floats
    __shared__ float sBhi[4096];
    __shared__ float sBlo[4096];

    int tid  = threadIdx.x;
    int wid  = tid >> 5;
    int lane = tid & 31;
    int g    = lane >> 2;     // group id (row / n offset)
    int t    = lane & 3;      // thread-in-group (k offset)

    int row0 = blockIdx.x * 128 + wid * 16;
    int rA = row0 + g;
    int rB = rA + 8;
    bool v0 = rA < n, v1 = rB < n;

    float4 acc[16];
    #pragma unroll
    for (int i = 0; i < 16; i++) acc[i] = make_float4(0.f, 0.f, 0.f, 0.f);

    const float* Abase0 = A + rA * 128 + t;
    const float* Abase1 = A + rB * 128 + t;

    for (int chunk = 0; chunk < 4; chunk++) {
        __syncthreads();
        // load + split B chunk (32 k-rows x 128 cols) into fragment layout
        #pragma unroll
        for (int i = 0; i < 16; i++) {
            int idx = tid + i * 256;
            int k  = idx >> 7;          // 0..31 within chunk
            int nn = idx & 127;         // 0..127 output col
            float w = B[(chunk * 32 + k) * 128 + nn];
            float hi = tf32r(w);
            float lo = tf32r(w - hi);
            int kstep = k >> 3, kk = k & 7;
            int tile = nn >> 3, tn = nn & 7;
            int addr = (((kstep * 16 + tile) * 32) + 4 * tn + (kk & 3)) * 2 + (kk >> 2);
            sBhi[addr] = hi;
            sBlo[addr] = lo;
        }
        __syncthreads();

        #pragma unroll
        for (int ks = 0; ks < 4; ks++) {
            int k0 = chunk * 32 + ks * 8;
            float x0 = v0 ? Abase0[k0]     : 0.f;   // (g,   t)
            float x1 = v1 ? Abase1[k0]     : 0.f;   // (g+8, t)
            float x2 = v0 ? Abase0[k0 + 4] : 0.f;   // (g,   t+4)
            float x3 = v1 ? Abase1[k0 + 4] : 0.f;   // (g+8, t+4)
            float h0 = tf32r(x0), h1 = tf32r(x1), h2 = tf32r(x2), h3 = tf32r(x3);
            float l0 = tf32r(x0 - h0), l1 = tf32r(x1 - h1);
            float l2 = tf32r(x2 - h2), l3 = tf32r(x3 - h3);
            unsigned ah0 = __float_as_uint(h0), ah1 = __float_as_uint(h1);
            unsigned ah2 = __float_as_uint(h2), ah3 = __float_as_uint(h3);
            unsigned al0 = __float_as_uint(l0), al1 = __float_as_uint(l1);
            unsigned al2 = __float_as_uint(l2), al3 = __float_as_uint(l3);

            const float2* bh2 = (const float2*)sBhi + (ks * 16) * 32 + lane;
            const float2* bl2 = (const float2*)sBlo + (ks * 16) * 32 + lane;
            #pragma unroll
            for (int tile = 0; tile < 16; tile++) {
                float2 bh = bh2[tile * 32];
                float2 bl = bl2[tile * 32];
                unsigned bh0 = __float_as_uint(bh.x), bh1 = __float_as_uint(bh.y);
                unsigned bl0 = __float_as_uint(bl.x), bl1 = __float_as_uint(bl.y);
                mma8(acc[tile], ah0, ah1, ah2, ah3, bh0, bh1);   // hi*hi
                mma8(acc[tile], ah0, ah1, ah2, ah3, bl0, bl1);   // hi*lo
                mma8(acc[tile], al0, al1, al2, al3, bh0, bh1);   // lo*hi
            }
        }
    }

    // store: c0,c1 -> (rA, tile*8 + 2t); c2,c3 -> (rB, same cols)
    #pragma unroll
    for (int tile = 0; tile < 16; tile++) {
        float2 o0 = make_float2(acc[tile].x, acc[tile].y);
        float2 o1 = make_float2(acc[tile].z, acc[tile].w);
        if (RELU) {
            o0.x = fmaxf(o0.x, 0.f); o0.y = fmaxf(o0.y, 0.f);
            o1.x = fmaxf(o1.x, 0.f); o1.y = fmaxf(o1.y, 0.f);
        }
        int col = tile * 8 + 2 * t;
        if (v0) *(float2*)(C + rA * 128 + col) = o0;
        if (v1) *(float2*)(C + rB * 128 + col) = o1;
    }
}

// ---------------- Fused epilogue: gate + relu + [128x10] projection ----------
__global__ void __launch_bounds__(256) epiK(const float* __restrict__ cc,
                                            const float* __restrict__ lam1,
                                            const float* __restrict__ lam2,
                                            const float* __restrict__ lw,
                                            const float* __restrict__ lb,
                                            float* __restrict__ out, int n) {
    __shared__ float sw[1280];
    int tid = threadIdx.x;
    for (int i = tid; i < 1280; i += 256) sw[i] = lw[i];
    __syncthreads();
    int w = (blockIdx.x << 3) + (tid >> 5);
    int lane = tid & 31;
    if (w >= n) return;

    float lamxl = 1.f / (1.f + expf(lam1[1] - lam1[0]));
    float laml  = 1.f - lamxl;
    float lamxh = 1.f / (1.f + expf(lam2[1] - lam2[0]));
    float lamh  = 1.f - lamxh;
    float m = cc[w];
    float lamx = lamxl * m + lamxh * (1.f - m);

    float4 fc = ((const float4*)g_bufE)[w * 32 + lane];
    float4 fl = ((const float4*)g_bufC)[w * 32 + lane];
    float4 fh = ((const float4*)g_bufD)[w * 32 + lane];
    float4 g;
    g.x = fmaxf(0.f, lamx * fc.x + laml * fl.x + lamh * fh.x);
    g.y = fmaxf(0.f, lamx * fc.y + laml * fl.y + lamh * fh.y);
    g.z = fmaxf(0.f, lamx * fc.z + laml * fl.z + lamh * fh.z);
    g.w = fmaxf(0.f, lamx * fc.w + laml * fl.w + lamh * fh.w);

    int base = lane * 40;  // (lane*4) * 10
    #pragma unroll
    for (int c = 0; c < 10; c++) {
        float p = g.x * sw[base + c] + g.y * sw[base + 10 + c] +
                  g.z * sw[base + 20 + c] + g.w * sw[base + 30 + c];
        #pragma unroll
        for (int off = 16; off > 0; off >>= 1)
            p += __shfl_xor_sync(0xffffffffu, p, off);
        if (lane == 0) out[w * 10 + c] = p + lb[c];
    }
}

// ---------------- Launch (kernel launches ONLY, no host API) ----------------
extern "C" void kernel_launch(void* const* d_in, const int* in_sizes, int n_in,
                              void* d_out, int out_size) {
    const float* x    = (const float*)d_in[0];
    const int*   ei   = (const int*)d_in[1];       // int32 (or int64 low-words; detected)
    const float* cc   = (const float*)d_in[2];
    const float* W1L  = (const float*)d_in[3];
    const float* W1H  = (const float*)d_in[4];
    const float* W2L  = (const float*)d_in[5];
    const float* W2H  = (const float*)d_in[6];
    const float* WX   = (const float*)d_in[7];
    const float* lam1 = (const float*)d_in[8];
    const float* lam2 = (const float*)d_in[9];
    const float* lw   = (const float*)d_in[10];
    const float* lb   = (const float*)d_in[11];
    float*       out  = (float*)d_out;

    int n = in_sizes[2];        // cc_mask element count == N
    int E = in_sizes[1] / 2;    // element count / 2, dtype-independent

    int nbN = (n + 255) / 256;
    int nbE = (E + 255) / 256;
    int nbW = (n + 7) / 8;      // warp-per-row kernels, 8 warps/block
    int nbG = (n + 127) / 128;  // GEMM 128-row tiles

    detectK<<<1, 256>>>(ei, in_sizes[1]);
    initK<<<nbN, 256>>>(n);
    countK<<<nbE, 256>>>(ei, cc, E, n);
    bsumK<<<nbN, 256>>>(n);
    bscanK<<<1, 512>>>(nbN, n);
    bfinalK<<<nbN, 256>>>(n);
    dinvK<<<nbN, 256>>>(cc, n);
    scatterK<<<nbE, 256>>>(ei, E, n);

    spmm1K<<<nbW, 256>>>(x, cc, n);                     // -> bufA (yl), bufB (yh)
    gemmT<0, 0, true ><<<nbG, 256>>>(nullptr, W1L, n);  // bufC = relu(bufA @ W1L)
    gemmT<1, 1, true ><<<nbG, 256>>>(nullptr, W1H, n);  // bufD = relu(bufB @ W1H)
    spmm2K<0><<<nbW, 256>>>(n);                         // bufA = Ahat_ll @ bufC
    spmm2K<1><<<nbW, 256>>>(n);                         // bufB = Ahat_hh @ bufD
    gemmT<0, 0, false><<<nbG, 256>>>(nullptr, W2L, n);  // bufC = bufA @ W2L  (xl)
    gemmT<1, 1, false><<<nbG, 256>>>(nullptr, W2H, n);  // bufD = bufB @ W2H  (xh)
    gemmT<2, 2, false><<<nbG, 256>>>(x, WX, n);         // bufE = x @ WX      (xc)
    epiK<<<nbW, 256>>>(cc, lam1, lam2, lw, lb, out, n);
}

// round 10
// speedup vs baseline: 1.4362x; 1.0729x over previous
#include <cuda_runtime.h>

// ---------------- Problem constants ----------------
#define NMAX 100352          // >= 100000 nodes
#define EMAX 1700000         // >= 1.6M edges
#define FEAT 128             // F == H == 128

// ---------------- Device scratch (no allocs allowed) ----------------
__device__ int   g_is64;
__device__ int   g_oddnz;
__device__ int   g_cnt[NMAX];
__device__ float g_summ[NMAX];
__device__ int   g_rowptr[NMAX + 1];
__device__ int   g_wcur[NMAX];
__device__ int   g_colind[EMAX];
__device__ int   g_bsum[512];
__device__ int   g_boff[512];
__device__ float2 g_dlh[NMAX];            // packed (dl, dh)
__device__ float g_dll[NMAX], g_dhh[NMAX];
__device__ float g_wll[NMAX], g_whh[NMAX];
__device__ float g_bufA[NMAX * FEAT];
__device__ float g_bufB[NMAX * FEAT];
__device__ float g_bufC[NMAX * FEAT];
__device__ float g_bufD[NMAX * FEAT];
__device__ float g_bufE[NMAX * FEAT];

// ---------------- tf32 helpers -----------------
__device__ __forceinline__ float tf32r(float x) {
    unsigned u;
    asm("cvt.rna.tf32.f32 %0, %1;" : "=r"(u) : "f"(x));
    return __uint_as_float(u);
}

__device__ __forceinline__ void mma8(float4& d,
                                     unsigned a0, unsigned a1, unsigned a2, unsigned a3,
                                     unsigned b0, unsigned b1) {
    asm("mma.sync.aligned.m16n8k8.row.col.f32.tf32.tf32.f32 "
        "{%0,%1,%2,%3}, {%4,%5,%6,%7}, {%8,%9}, {%0,%1,%2,%3};"
        : "+f"(d.x), "+f"(d.y), "+f"(d.z), "+f"(d.w)
        : "r"(a0), "r"(a1), "r"(a2), "r"(a3), "r"(b0), "r"(b1));
}

// ---------------- dtype detector: int32 vs int64 edge_index -------------
__global__ void detectK(const int* __restrict__ ei, int nwords) {
    if (threadIdx.x == 0) g_oddnz = 0;
    __syncthreads();
    int lim = nwords < 4096 ? nwords : 4096;
    for (int i = 1 + 2 * (int)threadIdx.x; i < lim; i += 2 * (int)blockDim.x)
        if (ei[i] != 0) atomicOr(&g_oddnz, 1);
    __syncthreads();
    if (threadIdx.x == 0) g_is64 = (g_oddnz == 0) ? 1 : 0;
}

__device__ __forceinline__ void edge_fetch(const int* ei, int E, int e,
                                           int& s, int& r) {
    if (g_is64) {          // int64 little-endian: low words at even positions
        s = ei[2 * e];
        r = ei[2 * E + 2 * e];
    } else {               // int32: [src x E, dst x E]
        s = ei[e];
        r = ei[E + e];
    }
}

// ---------------- Preprocessing ----------------
__global__ void initK(int n) {
    int i = blockIdx.x * blockDim.x + threadIdx.x;
    if (i < n) { g_cnt[i] = 0; g_summ[i] = 0.f; }
}

__global__ void countK(const int* __restrict__ ei,
                       const float* __restrict__ cc, int E, int n) {
    int e = blockIdx.x * blockDim.x + threadIdx.x;
    if (e >= E) return;
    int s, r;
    edge_fetch(ei, E, e, s, r);
    if (s != r && (unsigned)s < (unsigned)n && (unsigned)r < (unsigned)n) {
        atomicAdd(&g_cnt[r], 1);
        atomicAdd(&g_summ[r], cc[s]);
    }
}

// ---------------- 3-phase grid scan over g_cnt -> rowptr, wcur ----------
__global__ void bsumK(int n) {
    __shared__ int sh[256];
    int t = threadIdx.x;
    int i = blockIdx.x * 256 + t;
    int v = (i < n) ? g_cnt[i] : 0;
    sh[t] = v;
    __syncthreads();
    for (int s = 128; s > 0; s >>= 1) {
        if (t < s) sh[t] += sh[t + s];
        __syncthreads();
    }
    if (t == 0) g_bsum[blockIdx.x] = sh[0];
}

__global__ void bscanK(int nb, int n) {   // 1 block, 512 threads
    __shared__ int sh[512];
    int t = threadIdx.x;
    int v = (t < nb) ? g_bsum[t] : 0;
    sh[t] = v;
    __syncthreads();
    for (int off = 1; off < 512; off <<= 1) {
        int u = (t >= off) ? sh[t - off] : 0;
        __syncthreads();
        sh[t] += u;
        __syncthreads();
    }
    g_boff[t] = sh[t] - v;                 // exclusive prefix
    if (t == 0) g_rowptr[n] = sh[511];     // grand total
}

__global__ void bfinalK(int n) {
    __shared__ int sh[256];
    int t = threadIdx.x;
    int i = blockIdx.x * 256 + t;
    int v = (i < n) ? g_cnt[i] : 0;
    sh[t] = v;
    __syncthreads();
    for (int off = 1; off < 256; off <<= 1) {
        int u = (t >= off) ? sh[t - off] : 0;
        __syncthreads();
        sh[t] += u;
        __syncthreads();
    }
    int excl = sh[t] - v + g_boff[blockIdx.x];
    if (i < n) { g_rowptr[i] = excl; g_wcur[i] = excl; }
}

__global__ void dinvK(const float* __restrict__ cc, int n) {
    int i = blockIdx.x * blockDim.x + threadIdx.x;
    if (i >= n) return;
    float m   = cc[i];
    float cnt = (float)g_cnt[i];
    float sm  = g_summ[i];
    float dl  = rsqrtf(m * cnt + 1.f);
    float dh  = rsqrtf((1.f - m) * cnt + 1.f);
    float dll = rsqrtf(sm + 1.f);
    float dhh = rsqrtf(cnt - sm + 1.f);
    g_dlh[i] = make_float2(dl, dh);
    g_dll[i] = dll; g_dhh[i] = dhh;
    g_wll[i] = m * dll;
    g_whh[i] = (1.f - m) * dhh;
}

__global__ void scatterK(const int* __restrict__ ei, int E, int n) {
    int e = blockIdx.x * blockDim.x + threadIdx.x;
    if (e >= E) return;
    int s, r;
    edge_fetch(ei, E, e, s, r);
    if (s != r && (unsigned)s < (unsigned)n && (unsigned)r < (unsigned)n) {
        int pos = atomicAdd(&g_wcur[r], 1);
        g_colind[pos] = s;
    }
}

// ---------------- SpMM: warp per destination row ----------------
__global__ void __launch_bounds__(256) spmm1K(const float* __restrict__ x,
                                              const float* __restrict__ cc, int n) {
    int w = (blockIdx.x * blockDim.x + threadIdx.x) >> 5;
    int lane = threadIdx.x & 31;
    if (w >= n) return;
    const float4* x4 = (const float4*)x;
    float4 al = make_float4(0.f, 0.f, 0.f, 0.f);
    float4 ah = make_float4(0.f, 0.f, 0.f, 0.f);
    int s = g_rowptr[w], e = g_rowptr[w + 1];
    for (int i = s; i < e; i++) {
        int c = g_colind[i];
        float2 wlh = g_dlh[c];
        float4 xv = __ldg(&x4[c * 32 + lane]);
        al.x = fmaf(wlh.x, xv.x, al.x); al.y = fmaf(wlh.x, xv.y, al.y);
        al.z = fmaf(wlh.x, xv.z, al.z); al.w = fmaf(wlh.x, xv.w, al.w);
        ah.x = fmaf(wlh.y, xv.x, ah.x); ah.y = fmaf(wlh.y, xv.y, ah.y);
        ah.z = fmaf(wlh.y, xv.z, ah.z); ah.w = fmaf(wlh.y, xv.w, ah.w);
    }
    float m = cc[w];
    float2 dlh = g_dlh[w];
    float4 xr = x4[w * 32 + lane];
    float sl = dlh.x * m, dl2 = dlh.x * dlh.x;
    float sh = dlh.y * (1.f - m), dh2 = dlh.y * dlh.y;
    float4 ol, oh;
    ol.x = fmaf(sl, al.x, dl2 * xr.x); ol.y = fmaf(sl, al.y, dl2 * xr.y);
    ol.z = fmaf(sl, al.z, dl2 * xr.z); ol.w = fmaf(sl, al.w, dl2 * xr.w);
    oh.x = fmaf(sh, ah.x, dh2 * xr.x); oh.y = fmaf(sh, ah.y, dh2 * xr.y);
    oh.z = fmaf(sh, ah.z, dh2 * xr.z); oh.w = fmaf(sh, ah.w, dh2 * xr.w);
    ((float4*)g_bufA)[w * 32 + lane] = ol;
    ((float4*)g_bufB)[w * 32 + lane] = oh;
}

// Layer 2 (source-masked). SEL=0: bufC->bufA with (wll,dll); SEL=1: bufD->bufB with (whh,dhh)
template<int SEL>
__global__ void __launch_bounds__(256) spmm2K(int n) {
    const float* in = (SEL == 0) ? g_bufC : g_bufD;
    float* out      = (SEL == 0) ? g_bufA : g_bufB;
    const float* wc = (SEL == 0) ? g_wll  : g_whh;
    const float* dr = (SEL == 0) ? g_dll  : g_dhh;
    int w = (blockIdx.x * blockDim.x + threadIdx.x) >> 5;
    int lane = threadIdx.x & 31;
    if (w >= n) return;
    const float4* in4 = (const float4*)in;
    float4 acc = make_float4(0.f, 0.f, 0.f, 0.f);
    int s = g_rowptr[w], e = g_rowptr[w + 1];
    for (int i = s; i < e; i++) {
        int c = g_colind[i];
        float ww = wc[c];
        float4 xv = __ldg(&in4[c * 32 + lane]);
        acc.x = fmaf(ww, xv.x, acc.x); acc.y = fmaf(ww, xv.y, acc.y);
        acc.z = fmaf(ww, xv.z, acc.z); acc.w = fmaf(ww, xv.w, acc.w);
    }
    float d = dr[w], d2 = d * d;
    float4 xr = in4[w * 32 + lane];
    float4 o;
    o.x = fmaf(d, acc.x, d2 * xr.x); o.y = fmaf(d, acc.y, d2 * xr.y);
    o.z = fmaf(d, acc.z, d2 * xr.z); o.w = fmaf(d, acc.w, d2 * xr.w);
    ((float4*)out)[w * 32 + lane] = o;
}

// ---------------- GEMM: [n x 128] @ [128 x 128] via 3xTF32 tensor mma -------
// Block: 128 rows, 8 warps; warp owns 16 rows x 128 cols (16 n8-tiles).
// Both A and B staged per 32-k chunk in fragment-ordered smem:
//   A: coalesced float4 LDG (each elem once/block) -> [wid][ks][lane][4],
//      fragment read = one conflict-free LDS.128; hi/lo split in regs.
//   B: [kstep][tile][lane][2] hi/lo pre-split.
// D += Ahi*Bhi + Ahi*Blo + Alo*Bhi  (3xTF32: fp32-grade accuracy).
// ASRC: 0=g_bufA, 1=g_bufB, 2=external (x). CDST: 0=g_bufC, 1=g_bufD, 2=g_bufE.
template<int ASRC, int CDST, bool RELU>
__global__ void __launch_bounds__(256) gemmT(const float* __restrict__ Aext,
                                             const float* __restrict__ B,
                                             int n) {
    const float* A = (ASRC == 0) ? g_bufA : (ASRC == 1) ? g_bufB : Aext;
    float* C       = (CDST == 0) ? g_bufC : (CDST == 1) ? g_bufD : g_bufE;

    __shared__ float sBhi[4096];   // 16 KB
    __shared__ float sBlo[4096];   // 16 KB
    __shared__ float sA[4096];     // 16 KB: [wid(8)][ks(4)][lane(32)][j(4)]

    int tid  = threadIdx.x;
    int wid  = tid >> 5;
    int lane = tid & 31;
    int g    = lane >> 2;     // group id (row / n offset)
    int t    = lane & 3;      // thread-in-group (k offset)

    int rowB = blockIdx.x * 128;
    int row0 = rowB + wid * 16;
    int rA = row0 + g;
    int rB = rA + 8;
    bool v0 = rA < n, v1 = rB < n;

    float4 acc[16];
    #pragma unroll
    for (int i = 0; i < 16; i++) acc[i] = make_float4(0.f, 0.f, 0.f, 0.f);

    const float4* A4 = (const float4*)A;

    for (int chunk = 0; chunk < 4; chunk++) {
        __syncthreads();
        // ---- stage B chunk (32 k-rows x 128 cols) into hi/lo fragment layout
        #pragma unroll
        for (int i = 0; i < 16; i++) {
            int idx = tid + i * 256;
            int k  = idx >> 7;          // 0..31 within chunk
            int nn = idx & 127;         // output col
            float w = B[(chunk * 32 + k) * 128 + nn];
            float hi = tf32r(w);
            float lo = tf32r(w - hi);
            int kstep = k >> 3, kk = k & 7;
            int tile = nn >> 3, tn = nn & 7;
            int addr = (((kstep * 16 + tile) * 32) + 4 * tn + (kk & 3)) * 2 + (kk >> 2);
            sBhi[addr] = hi;
            sBlo[addr] = lo;
        }
        // ---- stage A chunk (128 rows x 32 k) coalesced -> fragment layout
        #pragma unroll
        for (int i = 0; i < 4; i++) {
            int idx = tid + i * 256;        // 0..1023
            int r = idx >> 3;               // row within tile 0..127
            int q = idx & 7;                // float4 index within 32-k chunk
            float4 v = (rowB + r < n) ? A4[(rowB + r) * 32 + chunk * 8 + q]
                                      : make_float4(0.f, 0.f, 0.f, 0.f);
            int w2 = r >> 4;                // owning warp
            int rw = r & 15;
            int gp = rw & 7, half = rw >> 3;
            #pragma unroll
            for (int j = 0; j < 4; j++) {
                int k = 4 * q + j;
                int ks = k >> 3, kk = k & 7;
                int addr = ((w2 * 4 + ks) * 32 + gp * 4 + (kk & 3)) * 4
                         + (half + 2 * (kk >> 2));
                float val = (j == 0) ? v.x : (j == 1) ? v.y : (j == 2) ? v.z : v.w;
                sA[addr] = val;
            }
        }
        __syncthreads();

        #pragma unroll
        for (int ks = 0; ks < 4; ks++) {
            float4 a = *(const float4*)&sA[((wid * 4 + ks) * 32 + lane) * 4];
            float h0 = tf32r(a.x), h1 = tf32r(a.y), h2 = tf32r(a.z), h3 = tf32r(a.w);
            float l0 = tf32r(a.x - h0), l1 = tf32r(a.y - h1);
            float l2 = tf32r(a.z - h2), l3 = tf32r(a.w - h3);
            unsigned ah0 = __float_as_uint(h0), ah1 = __float_as_uint(h1);
            unsigned ah2 = __float_as_uint(h2), ah3 = __float_as_uint(h3);
            unsigned al0 = __float_as_uint(l0), al1 = __float_as_uint(l1);
            unsigned al2 = __float_as_uint(l2), al3 = __float_as_uint(l3);

            const float2* bh2 = (const float2*)sBhi + (ks * 16) * 32 + lane;
            const float2* bl2 = (const float2*)sBlo + (ks * 16) * 32 + lane;
            #pragma unroll
            for (int tile = 0; tile < 16; tile++) {
                float2 bh = bh2[tile * 32];
                float2 bl = bl2[tile * 32];
                unsigned bh0 = __float_as_uint(bh.x), bh1 = __float_as_uint(bh.y);
                unsigned bl0 = __float_as_uint(bl.x), bl1 = __float_as_uint(bl.y);
                mma8(acc[tile], ah0, ah1, ah2, ah3, bh0, bh1);   // hi*hi
                mma8(acc[tile], ah0, ah1, ah2, ah3, bl0, bl1);   // hi*lo
                mma8(acc[tile], al0, al1, al2, al3, bh0, bh1);   // lo*hi
            }
        }
    }

    // store: c0,c1 -> (rA, tile*8 + 2t); c2,c3 -> (rB, same cols)
    #pragma unroll
    for (int tile = 0; tile < 16; tile++) {
        float2 o0 = make_float2(acc[tile].x, acc[tile].y);
        float2 o1 = make_float2(acc[tile].z, acc[tile].w);
        if (RELU) {
            o0.x = fmaxf(o0.x, 0.f); o0.y = fmaxf(o0.y, 0.f);
            o1.x = fmaxf(o1.x, 0.f); o1.y = fmaxf(o1.y, 0.f);
        }
        int col = tile * 8 + 2 * t;
        if (v0) *(float2*)(C + rA * 128 + col) = o0;
        if (v1) *(float2*)(C + rB * 128 + col) = o1;
    }
}

// ---------------- Fused epilogue: gate + relu + [128x10] projection ----------
__global__ void __launch_bounds__(256) epiK(const float* __restrict__ cc,
                                            const float* __restrict__ lam1,
                                            const float* __restrict__ lam2,
                                            const float* __restrict__ lw,
                                            const float* __restrict__ lb,
                                            float* __restrict__ out, int n) {
    __shared__ float sw[1280];
    int tid = threadIdx.x;
    for (int i = tid; i < 1280; i += 256) sw[i] = lw[i];
    __syncthreads();
    int w = (blockIdx.x << 3) + (tid >> 5);
    int lane = tid & 31;
    if (w >= n) return;

    float lamxl = 1.f / (1.f + expf(lam1[1] - lam1[0]));
    float laml  = 1.f - lamxl;
    float lamxh = 1.f / (1.f + expf(lam2[1] - lam2[0]));
    float lamh  = 1.f - lamxh;
    float m = cc[w];
    float lamx = lamxl * m + lamxh * (1.f - m);

    float4 fc = ((const float4*)g_bufE)[w * 32 + lane];
    float4 fl = ((const float4*)g_bufC)[w * 32 + lane];
    float4 fh = ((const float4*)g_bufD)[w * 32 + lane];
    float4 g;
    g.x = fmaxf(0.f, lamx * fc.x + laml * fl.x + lamh * fh.x);
    g.y = fmaxf(0.f, lamx * fc.y + laml * fl.y + lamh * fh.y);
    g.z = fmaxf(0.f, lamx * fc.z + laml * fl.z + lamh * fh.z);
    g.w = fmaxf(0.f, lamx * fc.w + laml * fl.w + lamh * fh.w);

    int base = lane * 40;  // (lane*4) * 10
    #pragma unroll
    for (int c = 0; c < 10; c++) {
        float p = g.x * sw[base + c] + g.y * sw[base + 10 + c] +
                  g.z * sw[base + 20 + c] + g.w * sw[base + 30 + c];
        #pragma unroll
        for (int off = 16; off > 0; off >>= 1)
            p += __shfl_xor_sync(0xffffffffu, p, off);
        if (lane == 0) out[w * 10 + c] = p + lb[c];
    }
}

// ---------------- Launch (kernel launches ONLY, no host API) ----------------
extern "C" void kernel_launch(void* const* d_in, const int* in_sizes, int n_in,
                              void* d_out, int out_size) {
    const float* x    = (const float*)d_in[0];
    const int*   ei   = (const int*)d_in[1];       // int32 (or int64 low-words; detected)
    const float* cc   = (const float*)d_in[2];
    const float* W1L  = (const float*)d_in[3];
    const float* W1H  = (const float*)d_in[4];
    const float* W2L  = (const float*)d_in[5];
    const float* W2H  = (const float*)d_in[6];
    const float* WX   = (const float*)d_in[7];
    const float* lam1 = (const float*)d_in[8];
    const float* lam2 = (const float*)d_in[9];
    const float* lw   = (const float*)d_in[10];
    const float* lb   = (const float*)d_in[11];
    float*       out  = (float*)d_out;

    int n = in_sizes[2];        // cc_mask element count == N
    int E = in_sizes[1] / 2;    // element count / 2, dtype-independent

    int nbN = (n + 255) / 256;
    int nbE = (E + 255) / 256;
    int nbW = (n + 7) / 8;      // warp-per-row kernels, 8 warps/block
    int nbG = (n + 127) / 128;  // GEMM 128-row tiles

    detectK<<<1, 256>>>(ei, in_sizes[1]);
    initK<<<nbN, 256>>>(n);
    countK<<<nbE, 256>>>(ei, cc, E, n);
    bsumK<<<nbN, 256>>>(n);
    bscanK<<<1, 512>>>(nbN, n);
    bfinalK<<<nbN, 256>>>(n);
    dinvK<<<nbN, 256>>>(cc, n);
    scatterK<<<nbE, 256>>>(ei, E, n);

    spmm1K<<<nbW, 256>>>(x, cc, n);                     // -> bufA (yl), bufB (yh)
    gemmT<0, 0, true ><<<nbG, 256>>>(nullptr, W1L, n);  // bufC = relu(bufA @ W1L)
    gemmT<1, 1, true ><<<nbG, 256>>>(nullptr, W1H, n);  // bufD = relu(bufB @ W1H)
    spmm2K<0><<<nbW, 256>>>(n);                         // bufA = Ahat_ll @ bufC
    spmm2K<1><<<nbW, 256>>>(n);                         // bufB = Ahat_hh @ bufD
    gemmT<0, 0, false><<<nbG, 256>>>(nullptr, W2L, n);  // bufC = bufA @ W2L  (xl)
    gemmT<1, 1, false><<<nbG, 256>>>(nullptr, W2H, n);  // bufD = bufB @ W2H  (xh)
    gemmT<2, 2, false><<<nbG, 256>>>(x, WX, n);         // bufE = x @ WX      (xc)
    epiK<<<nbW, 256>>>(cc, lam1, lam2, lw, lb, out, n);
}